// round 1
// baseline (speedup 1.0000x reference)
#include <cuda_runtime.h>
#include <math.h>

// Problem constants (B=4, T=2048)
#define NTOK   8192      // B*T
#define DM     2048      // d_model
#define DE     1024      // d_expert (== d_ff of routed experts)
#define NE     8         // experts
#define TOPK   2
#define CAP    2560      // ceil(NTOK*TOPK/NE * 1.25)
#define NR     (NTOK*TOPK)   // 16384 routes
#define NCHUNK 64
#define CHUNK  256           // NCHUNK*CHUNK == NR

// ---------------- scratch (device globals; allocation-free) ----------------
__device__ float g_s[NTOK * NE];            // softmax probs (for importance)
__device__ float g_gsh[NTOK];               // sigmoid gate for shared expert
__device__ int   g_tope[NR];                // top-k expert per route
__device__ float g_topg[NR];                // top-k gate value per route
__device__ int   g_partial[NCHUNK * NE];
__device__ int   g_choff[NCHUNK * NE];
__device__ int   g_counts[NE];              // pre-capacity counts (for load stat)
__device__ int   g_ckept[NE];               // min(count, CAP)
__device__ int   g_etok[NE * CAP];          // token index per (expert, slot)
__device__ int   g_rslot[NR];               // route -> global slot (e*CAP+pos) or -1
__device__ float g_h[NE * CAP * DE];        // 80 MB; expert hidden, reused for shared hidden
__device__ float g_slots[NE * CAP * DM];    // 160 MB; expert outputs per slot

// ---------------- router: logits, softmax, top-2, shared gate ----------------
__global__ void router_kernel(const float* __restrict__ x,
                              const float* __restrict__ rw,
                              const float* __restrict__ gw) {
    int n = blockIdx.x;
    const float* xr = x + (size_t)n * DM;
    int t = threadIdx.x;            // 256 threads = 8 warps
    int w = t >> 5, lane = t & 31;
    __shared__ float sm[9];

    // each warp: one expert dot product
    const float* wr = rw + w * DM;
    float acc = 0.f;
    for (int k = lane; k < DM; k += 32) acc += xr[k] * wr[k];
    #pragma unroll
    for (int o = 16; o; o >>= 1) acc += __shfl_xor_sync(0xffffffffu, acc, o);
    if (lane == 0) sm[w] = acc;

    // warp 0 additionally computes the shared-gate dot
    if (w == 0) {
        float g = 0.f;
        for (int k = lane; k < DM; k += 32) g += xr[k] * gw[k];
        #pragma unroll
        for (int o = 16; o; o >>= 1) g += __shfl_xor_sync(0xffffffffu, g, o);
        if (lane == 0) sm[8] = g;
    }
    __syncthreads();

    if (t == 0) {
        float l[NE];
        float mx = -1e30f;
        #pragma unroll
        for (int e = 0; e < NE; e++) { l[e] = sm[e]; mx = fmaxf(mx, l[e]); }
        float den = 0.f;
        #pragma unroll
        for (int e = 0; e < NE; e++) { l[e] = expf(l[e] - mx); den += l[e]; }
        float inv = 1.f / den;
        int b0 = 0; float v0 = -1.f;
        #pragma unroll
        for (int e = 0; e < NE; e++) {
            float p = l[e] * inv;
            g_s[n * NE + e] = p;
            if (p > v0) { v0 = p; b0 = e; }   // strict > : first index wins ties (matches top_k)
        }
        int b1 = 0; float v1 = -1.f;
        #pragma unroll
        for (int e = 0; e < NE; e++) {
            if (e == b0) continue;
            float p = l[e] * inv;
            if (p > v1) { v1 = p; b1 = e; }
        }
        g_tope[2 * n]     = b0;  g_topg[2 * n]     = v0;
        g_tope[2 * n + 1] = b1;  g_topg[2 * n + 1] = v1;
        g_gsh[n] = 1.f / (1.f + expf(-sm[8]));
    }
}

// ---------------- dispatch bookkeeping (stable, deterministic) ----------------
__global__ void hist_kernel() {
    __shared__ int h[NE];
    int t = threadIdx.x;
    if (t < NE) h[t] = 0;
    __syncthreads();
    atomicAdd(&h[g_tope[blockIdx.x * CHUNK + t]], 1);
    __syncthreads();
    if (t < NE) g_partial[blockIdx.x * NE + t] = h[t];
}

__global__ void scan_kernel() {
    int e = threadIdx.x;
    if (e >= NE) return;
    int run = 0;
    for (int b = 0; b < NCHUNK; b++) { g_choff[b * NE + e] = run; run += g_partial[b * NE + e]; }
    g_counts[e] = run;
    g_ckept[e] = run < CAP ? run : CAP;
}

__global__ void build_kernel() {
    if (threadIdx.x) return;
    int b = blockIdx.x;
    int cnt[NE];
    #pragma unroll
    for (int e = 0; e < NE; e++) cnt[e] = g_choff[b * NE + e];
    for (int i = 0; i < CHUNK; i++) {
        int r = b * CHUNK + i;
        int e = g_tope[r];
        int p = cnt[e]++;
        if (p < CAP) { g_etok[e * CAP + p] = r >> 1; g_rslot[r] = e * CAP + p; }
        else         { g_rslot[r] = -1; }
    }
}

// ---------------- tiled SGEMM with gather + fused epilogues ----------------
// Out[m,f] = sum_k A[m,k] * W[k,f]        (WT=false; W row-major [K,F])
// Out[m,f] = sum_k A[m,k] * W[f,k]        (WT=true;  W row-major [F,K])
// EPI: 0 = none, 1 = exact GELU, 2 = scale by gsh[m] (write, not add)
__device__ __forceinline__ float gelu_exact(float v) {
    return 0.5f * v * (1.0f + erff(v * 0.70710678118654752f));
}

template<bool WT, int EPI>
__global__ void __launch_bounds__(256)
sgemm_kernel(const float* __restrict__ X, const int* __restrict__ gidx,
             int ldx, int strideXrow,
             const float* __restrict__ W, long long strideW,
             float* __restrict__ Out, long long strideOut, int ldo,
             const int* __restrict__ Mcnts, int Mfixed,
             int F, int Kd, const float* __restrict__ gsh) {
    const int z = blockIdx.z;
    const int M = Mcnts ? Mcnts[z] : Mfixed;
    const int m0 = blockIdx.y * 128;
    if (m0 >= M) return;
    const int n0 = blockIdx.x * 64;

    const float* Wz = W + (size_t)z * strideW;
    float* Oz = Out + (size_t)z * strideOut;
    const int* idxz = gidx ? gidx + z * CAP : nullptr;
    const long long rowbase = (long long)z * strideXrow;

    __shared__ __align__(16) float As[16 * 128];   // transposed: As[k][m]
    __shared__ __align__(16) float Bs[16 * 64];    // Bs[k][f]

    const int tid = threadIdx.x;
    const int ty = tid >> 4, tx = tid & 15;

    float acc[8][4];
    #pragma unroll
    for (int i = 0; i < 8; i++)
        #pragma unroll
        for (int j = 0; j < 4; j++) acc[i][j] = 0.f;

    // A-tile load plan: 512 float4 per tile, 2 per thread
    const int q0 = tid * 2;
    const int ar0 = q0 >> 2,       ak0 = (q0 & 3) * 4;
    const int ar1 = (q0 + 1) >> 2, ak1 = ((q0 + 1) & 3) * 4;
    const bool va0 = (m0 + ar0) < M;
    const bool va1 = (m0 + ar1) < M;
    const long long gr0 = va0 ? (idxz ? (long long)idxz[m0 + ar0] : rowbase + m0 + ar0) : 0;
    const long long gr1 = va1 ? (idxz ? (long long)idxz[m0 + ar1] : rowbase + m0 + ar1) : 0;
    const float* pa0 = X + gr0 * ldx;
    const float* pa1 = X + gr1 * ldx;

    for (int k0 = 0; k0 < Kd; k0 += 16) {
        float4 a = va0 ? *(const float4*)(pa0 + k0 + ak0) : make_float4(0, 0, 0, 0);
        As[(ak0 + 0) * 128 + ar0] = a.x; As[(ak0 + 1) * 128 + ar0] = a.y;
        As[(ak0 + 2) * 128 + ar0] = a.z; As[(ak0 + 3) * 128 + ar0] = a.w;
        a = va1 ? *(const float4*)(pa1 + k0 + ak1) : make_float4(0, 0, 0, 0);
        As[(ak1 + 0) * 128 + ar1] = a.x; As[(ak1 + 1) * 128 + ar1] = a.y;
        As[(ak1 + 2) * 128 + ar1] = a.z; As[(ak1 + 3) * 128 + ar1] = a.w;

        if (!WT) {
            const int bk = tid >> 4, bf = (tid & 15) * 4;
            float4 b = *(const float4*)(Wz + (size_t)(k0 + bk) * F + n0 + bf);
            *(float4*)&Bs[bk * 64 + bf] = b;
        } else {
            const int bf = tid >> 2, bk = (tid & 3) * 4;
            float4 b = *(const float4*)(Wz + (size_t)(n0 + bf) * Kd + k0 + bk);
            Bs[(bk + 0) * 64 + bf] = b.x; Bs[(bk + 1) * 64 + bf] = b.y;
            Bs[(bk + 2) * 64 + bf] = b.z; Bs[(bk + 3) * 64 + bf] = b.w;
        }
        __syncthreads();

        #pragma unroll
        for (int kk = 0; kk < 16; kk++) {
            float4 a0 = *(const float4*)&As[kk * 128 + ty * 8];
            float4 a1 = *(const float4*)&As[kk * 128 + ty * 8 + 4];
            float4 b  = *(const float4*)&Bs[kk * 64 + tx * 4];
            float av[8] = {a0.x, a0.y, a0.z, a0.w, a1.x, a1.y, a1.z, a1.w};
            float bv[4] = {b.x, b.y, b.z, b.w};
            #pragma unroll
            for (int i = 0; i < 8; i++)
                #pragma unroll
                for (int j = 0; j < 4; j++)
                    acc[i][j] = fmaf(av[i], bv[j], acc[i][j]);
        }
        __syncthreads();
    }

    #pragma unroll
    for (int i = 0; i < 8; i++) {
        const int m = m0 + ty * 8 + i;
        float4 v = make_float4(acc[i][0], acc[i][1], acc[i][2], acc[i][3]);
        if (EPI == 1) {
            v.x = gelu_exact(v.x); v.y = gelu_exact(v.y);
            v.z = gelu_exact(v.z); v.w = gelu_exact(v.w);
        } else if (EPI == 2) {
            const float g = gsh[m];
            v.x *= g; v.y *= g; v.z *= g; v.w *= g;
        }
        *(float4*)(Oz + (size_t)m * ldo + n0 + tx * 4) = v;
    }
}

// ---------------- combine: out += sum of kept routed contributions ----------------
__global__ void combine_kernel(float* __restrict__ out) {
    const int n = blockIdx.x;
    const int s0 = g_rslot[2 * n], s1 = g_rslot[2 * n + 1];
    const float g0 = g_topg[2 * n], g1 = g_topg[2 * n + 1];
    float* o = out + (size_t)n * DM;
    for (int d = threadIdx.x * 4; d < DM; d += 1024) {
        float4 v = *(float4*)&o[d];
        if (s0 >= 0) {
            float4 a = *(const float4*)&g_slots[(size_t)s0 * DM + d];
            v.x += g0 * a.x; v.y += g0 * a.y; v.z += g0 * a.z; v.w += g0 * a.w;
        }
        if (s1 >= 0) {
            float4 a = *(const float4*)&g_slots[(size_t)s1 * DM + d];
            v.x += g1 * a.x; v.y += g1 * a.y; v.z += g1 * a.z; v.w += g1 * a.w;
        }
        *(float4*)&o[d] = v;
    }
}

// ---------------- stats ----------------
__global__ void importance_kernel(float* __restrict__ out) {
    const int e = blockIdx.x;
    const int t = threadIdx.x;
    float s = 0.f;
    for (int i = t; i < NTOK; i += 256) s += g_s[i * NE + e];
    __shared__ float red[256];
    red[t] = s; __syncthreads();
    for (int o = 128; o; o >>= 1) { if (t < o) red[t] += red[t + o]; __syncthreads(); }
    if (t == 0) out[(size_t)NTOK * DM + e] = red[0] / (float)NTOK;
}

__global__ void load_kernel(float* __restrict__ out) {
    const int e = threadIdx.x;
    if (e < NE) out[(size_t)NTOK * DM + NE + e] = (float)g_counts[e] / (float)NR;
}

// ---------------- launch ----------------
extern "C" void kernel_launch(void* const* d_in, const int* in_sizes, int n_in,
                              void* d_out, int out_size) {
    const float* x   = (const float*)d_in[0];   // [B,T,DM]
    const float* rw  = (const float*)d_in[1];   // [E,DM]
    const float* gw  = (const float*)d_in[2];   // [1,DM]
    const float* w1  = (const float*)d_in[3];   // [E,DM,DE]
    const float* w2  = (const float*)d_in[4];   // [E,DE,DM]
    const float* sw1 = (const float*)d_in[5];   // [DFF,DM] (NT)
    const float* sw2 = (const float*)d_in[6];   // [DM,DFF] (NT)
    float* out = (float*)d_out;

    void *p_etok, *p_ckept, *p_h, *p_slots, *p_gsh;
    cudaGetSymbolAddress(&p_etok,  g_etok);
    cudaGetSymbolAddress(&p_ckept, g_ckept);
    cudaGetSymbolAddress(&p_h,     g_h);
    cudaGetSymbolAddress(&p_slots, g_slots);
    cudaGetSymbolAddress(&p_gsh,   g_gsh);

    router_kernel<<<NTOK, 256>>>(x, rw, gw);
    hist_kernel<<<NCHUNK, CHUNK>>>();
    scan_kernel<<<1, 32>>>();
    build_kernel<<<NCHUNK, 32>>>();

    // expert pass 1: h = gelu(x[tok] @ w1[e])   [M<=CAP, DE], K=DM, NN
    dim3 gp1(DE / 64, CAP / 128, NE);
    sgemm_kernel<false, 1><<<gp1, 256>>>(x, (const int*)p_etok, DM, 0,
                                         w1, (long long)DM * DE,
                                         (float*)p_h, (long long)CAP * DE, DE,
                                         (const int*)p_ckept, 0, DE, DM, nullptr);
    // expert pass 2: slots = h @ w2[e]          [M<=CAP, DM], K=DE, NN
    dim3 gp2(DM / 64, CAP / 128, NE);
    sgemm_kernel<false, 0><<<gp2, 256>>>((const float*)p_h, nullptr, DE, CAP,
                                         w2, (long long)DE * DM,
                                         (float*)p_slots, (long long)CAP * DM, DM,
                                         (const int*)p_ckept, 0, DM, DE, nullptr);
    // shared pass 1: h = gelu(x @ sw1^T)        [NTOK, DE], K=DM, NT
    dim3 gs1(DE / 64, NTOK / 128, 1);
    sgemm_kernel<true, 1><<<gs1, 256>>>(x, nullptr, DM, 0,
                                        sw1, 0,
                                        (float*)p_h, 0, DE,
                                        nullptr, NTOK, DE, DM, nullptr);
    // shared pass 2: out = gsh * (h @ sw2^T)    [NTOK, DM], K=DE, NT
    dim3 gs2(DM / 64, NTOK / 128, 1);
    sgemm_kernel<true, 2><<<gs2, 256>>>((const float*)p_h, nullptr, DE, 0,
                                        sw2, 0,
                                        out, 0, DM,
                                        nullptr, NTOK, DM, DE, (const float*)p_gsh);

    combine_kernel<<<NTOK, 256>>>(out);

    if (out_size >= NTOK * DM + 2 * NE) {
        importance_kernel<<<NE, 256>>>(out);
        load_kernel<<<1, NE>>>(out);
    }
}